// round 1
// baseline (speedup 1.0000x reference)
#include <cuda_runtime.h>
#include <cstdint>

#define B_   2
#define C_   384
#define L_   8192
#define DIN  768
#define NST  16
#define DTR  24
#define XW   56        // dt_rank + 2*d_state

// ---------------- scratch (device globals; no allocation allowed) ----------------
__device__ float g_stats[B_*L_*2];        // mu, rstd per (b,l)
__device__ float g_xn  [(size_t)B_*L_*C_];     // (b*l, c)
__device__ float g_xi  [(size_t)B_*L_*DIN];    // (b*l, d)
__device__ float g_z   [(size_t)B_*L_*DIN];    // (b*l, d)
__device__ float g_xct [(size_t)B_*DIN*L_];    // (b, d, l)  conv+silu output
__device__ float g_xdbl[(size_t)B_*L_*XW];     // (b*l, 56)
__device__ float g_dtt [(size_t)B_*DIN*L_];    // (b, d, l)  softplus(dt)
__device__ float g_yt  [(size_t)B_*DIN*L_];    // (b, d, l)  scan out + x*D (pre-gate)

// ---------------- f32x2 packed-FMA helpers (FFMA2 path, sm_100+) ----------------
typedef unsigned long long u64;
__device__ __forceinline__ void ffma2(u64 &d, u64 a, u64 b) {
    asm("fma.rn.f32x2 %0, %1, %2, %0;" : "+l"(d) : "l"(a), "l"(b));
}
__device__ __forceinline__ u64 pack2(float lo, float hi) {
    u64 r; asm("mov.b64 %0, {%1, %2};" : "=l"(r) : "f"(lo), "f"(hi)); return r;
}
__device__ __forceinline__ float2 unpack2(u64 v) {
    float2 r; asm("mov.b64 {%0, %1}, %2;" : "=f"(r.x), "=f"(r.y) : "l"(v)); return r;
}
__device__ __forceinline__ float silu_f(float v) {
    return v * (1.f / (1.f + __expf(-v)));
}

// ---------------- 1) LayerNorm stats ----------------
__global__ void ln_stats_kernel(const float* __restrict__ x) {
    int t = blockIdx.x * blockDim.x + threadIdx.x;   // 0..B*L-1
    int b = t / L_, l = t % L_;
    const float* p = x + (size_t)b * C_ * L_ + l;
    float s = 0.f, ss = 0.f;
    #pragma unroll 4
    for (int c = 0; c < C_; c++) { float v = p[(size_t)c * L_]; s += v; ss += v * v; }
    float mu = s * (1.f / C_);
    float var = ss * (1.f / C_) - mu * mu;
    g_stats[2*t]   = mu;
    g_stats[2*t+1] = rsqrtf(var + 1e-5f);
}

// ---------------- 2) LayerNorm apply + transpose (b,c,l) -> (b*l, c) ----------------
__global__ void ln_apply_kernel(const float* __restrict__ x, const float* __restrict__ w,
                                const float* __restrict__ bb) {
    __shared__ float t[32][33];
    int c0 = blockIdx.x * 32, l0 = blockIdx.y * 32, b = blockIdx.z;
    int tx = threadIdx.x & 31, ty = threadIdx.x >> 5;   // ty 0..7
    const float* xb = x + (size_t)b * C_ * L_;
    #pragma unroll
    for (int p = 0; p < 4; p++) {
        int c = c0 + ty + p*8;
        t[ty + p*8][tx] = xb[(size_t)c * L_ + l0 + tx];
    }
    __syncthreads();
    #pragma unroll
    for (int p = 0; p < 4; p++) {
        int l = l0 + ty + p*8;
        int c = c0 + tx;
        int li = b * L_ + l;
        float mu = g_stats[2*li], rs = g_stats[2*li+1];
        float v = (t[tx][ty + p*8] - mu) * rs * w[c] + bb[c];
        g_xn[(size_t)li * C_ + c] = v;
    }
}

// ---------------- 3) GEMM: xz = xn @ W_in^T, split into xi / z ----------------
// M=16384, K=384, N=1536. 128x128x8 tile, 256 thr, 8x8 frag via f32x2.
__global__ void gemm_in_kernel(const float* __restrict__ W) {
    __shared__ __align__(16) float As[8][128];
    __shared__ __align__(16) float Bs[8][128];
    int bm = blockIdx.y, bn = blockIdx.x;
    int tid = threadIdx.x;
    int tc = tid & 15, tr = tid >> 4;
    u64 acc[8][4];
    #pragma unroll
    for (int i = 0; i < 8; i++)
        #pragma unroll
        for (int j = 0; j < 4; j++) acc[i][j] = 0ull;
    int lr = tid >> 1;
    int lk = (tid & 1) * 4;
    const float* Ag = g_xn + ((size_t)bm*128 + lr) * C_ + lk;
    const float* Wg = W    + ((size_t)bn*128 + lr) * C_ + lk;
    for (int k0 = 0; k0 < C_; k0 += 8) {
        float4 av = *(const float4*)(Ag + k0);
        float4 bv = *(const float4*)(Wg + k0);
        As[lk+0][lr]=av.x; As[lk+1][lr]=av.y; As[lk+2][lr]=av.z; As[lk+3][lr]=av.w;
        Bs[lk+0][lr]=bv.x; Bs[lk+1][lr]=bv.y; Bs[lk+2][lr]=bv.z; Bs[lk+3][lr]=bv.w;
        __syncthreads();
        #pragma unroll
        for (int k = 0; k < 8; k++) {
            float ar[8];
            *(float4*)&ar[0] = *(const float4*)&As[k][tr*8];
            *(float4*)&ar[4] = *(const float4*)&As[k][tr*8+4];
            u64 br[4];
            *(float4*)&br[0] = *(const float4*)&Bs[k][tc*8];
            *(float4*)&br[2] = *(const float4*)&Bs[k][tc*8+4];
            #pragma unroll
            for (int i = 0; i < 8; i++) {
                u64 ai = pack2(ar[i], ar[i]);
                #pragma unroll
                for (int j = 0; j < 4; j++) ffma2(acc[i][j], ai, br[j]);
            }
        }
        __syncthreads();
    }
    int col0 = bn*128 + tc*8;
    float* dst; int cofs;
    if (col0 < DIN) { dst = g_xi; cofs = col0; } else { dst = g_z; cofs = col0 - DIN; }
    #pragma unroll
    for (int i = 0; i < 8; i++) {
        int row = bm*128 + tr*8 + i;
        float2 p0 = unpack2(acc[i][0]), p1 = unpack2(acc[i][1]);
        float2 p2 = unpack2(acc[i][2]), p3 = unpack2(acc[i][3]);
        float4 v0 = {p0.x, p0.y, p1.x, p1.y};
        float4 v1 = {p2.x, p2.y, p3.x, p3.y};
        *(float4*)(dst + (size_t)row*DIN + cofs)     = v0;
        *(float4*)(dst + (size_t)row*DIN + cofs + 4) = v1;
    }
}

// ---------------- 4) depthwise causal conv (k=4) + SiLU, (b,l,d) -> (b,d,l) ----------------
__global__ void conv_silu_kernel(const float* __restrict__ cw, const float* __restrict__ cb) {
    __shared__ float s[67][33];
    int l0 = blockIdx.x * 64, d0 = blockIdx.y * 32, b = blockIdx.z;
    int tid = threadIdx.x;
    for (int idx = tid; idx < 67*32; idx += 256) {
        int li = idx >> 5, dd = idx & 31;
        int gl = l0 + li - 3;
        s[li][dd] = (gl >= 0) ? g_xi[((size_t)(b*L_ + gl))*DIN + d0 + dd] : 0.f;
    }
    __syncthreads();
    for (int idx = tid; idx < 2048; idx += 256) {
        int dd = idx >> 6, ll = idx & 63;
        int d = d0 + dd;
        float w0 = cw[d*4], w1 = cw[d*4+1], w2 = cw[d*4+2], w3 = cw[d*4+3];
        float acc = cb[d];
        acc += w0*s[ll][dd] + w1*s[ll+1][dd] + w2*s[ll+2][dd] + w3*s[ll+3][dd];
        g_xct[((size_t)(b*DIN + d))*L_ + l0 + ll] = silu_f(acc);
    }
}

// ---------------- 5) GEMM: x_dbl = xc @ W_xproj^T  (N=56, A read from (b,d,l)) ----------------
__global__ void gemm_xproj_kernel(const float* __restrict__ Wx) {
    __shared__ float As[16][128];
    __shared__ float Bs[16][56];
    int row0 = blockIdx.x * 128;
    int b = row0 / L_, l0 = row0 % L_;
    int tid = threadIdx.x;
    float acc[4][7];
    #pragma unroll
    for (int i = 0; i < 4; i++)
        #pragma unroll
        for (int j = 0; j < 7; j++) acc[i][j] = 0.f;
    int mr = (tid >> 3) * 4;   // 0..124
    int nc = (tid & 7) * 7;    // 0..49
    for (int k0 = 0; k0 < DIN; k0 += 16) {
        for (int idx = tid; idx < 2048; idx += 256) {
            int kk = idx >> 7, lo = idx & 127;
            As[kk][lo] = g_xct[((size_t)(b*DIN + k0 + kk))*L_ + l0 + lo];
        }
        for (int idx = tid; idx < 896; idx += 256) {
            int r = idx / 16, kk = idx % 16;
            Bs[kk][r] = Wx[(size_t)r*DIN + k0 + kk];
        }
        __syncthreads();
        #pragma unroll
        for (int k = 0; k < 16; k++) {
            float ar[4], br[7];
            #pragma unroll
            for (int i = 0; i < 4; i++) ar[i] = As[k][mr+i];
            #pragma unroll
            for (int j = 0; j < 7; j++) br[j] = Bs[k][nc+j];
            #pragma unroll
            for (int i = 0; i < 4; i++)
                #pragma unroll
                for (int j = 0; j < 7; j++) acc[i][j] = fmaf(ar[i], br[j], acc[i][j]);
        }
        __syncthreads();
    }
    #pragma unroll
    for (int i = 0; i < 4; i++)
        #pragma unroll
        for (int j = 0; j < 7; j++)
            g_xdbl[(size_t)(row0 + mr + i)*XW + nc + j] = acc[i][j];
}

// ---------------- 6) dt = softplus(x_dbl[:, :24] @ W_dt^T + b_dt) -> (b,d,l) ----------------
__global__ void dt_kernel(const float* __restrict__ Wdt, const float* __restrict__ bdt) {
    __shared__ float xs[32][25];
    __shared__ float ws[64][24];
    __shared__ float bs[64];
    int l0 = blockIdx.x * 32, d0 = blockIdx.y * 64, b = blockIdx.z;
    int tid = threadIdx.x;
    for (int idx = tid; idx < 32*24; idx += 256) {
        int ll = idx / 24, r = idx % 24;
        xs[ll][r] = g_xdbl[(size_t)(b*L_ + l0 + ll)*XW + r];
    }
    for (int idx = tid; idx < 64*24; idx += 256) {
        int dd = idx / 24, r = idx % 24;
        ws[dd][r] = Wdt[(size_t)(d0+dd)*DTR + r];
    }
    if (tid < 64) bs[tid] = bdt[d0 + tid];
    __syncthreads();
    #pragma unroll
    for (int t = 0; t < 8; t++) {
        int idx = tid + t*256;
        int dd = idx >> 5, ll = idx & 31;
        float acc = bs[dd];
        #pragma unroll
        for (int r = 0; r < 24; r++) acc = fmaf(xs[ll][r], ws[dd][r], acc);
        float sp = (acc > 20.f) ? acc : log1pf(expf(acc));
        g_dtt[((size_t)(b*DIN + d0 + dd))*L_ + l0 + ll] = sp;
    }
}

// ---------------- 7) selective scan: warp = 2 (b,d) channels, 16 lanes = n states ----------------
__global__ void scan_kernel(const float* __restrict__ Alog, const float* __restrict__ Dp) {
    int gw = (blockIdx.x * blockDim.x + threadIdx.x) >> 5;   // 0..767
    int lane = threadIdx.x & 31;
    int half = lane >> 4, n = lane & 15;
    int b = gw / (DIN/2);
    int d = (gw % (DIN/2)) * 2 + half;
    const float* dtp = g_dtt + (size_t)(b*DIN + d) * L_;
    const float* xp  = g_xct + (size_t)(b*DIN + d) * L_;
    const float* bcp = g_xdbl + (size_t)b * L_ * XW + DTR + n;   // B at +0, C at +16
    float a  = -__expf(Alog[d*NST + n]);
    float Dd = Dp[d];
    float* yp = g_yt + (size_t)(b*DIN + d) * L_;
    float h = 0.f;
    const int U = 8;
    float cd[U], cx[U], cB[U], cC[U];
    #pragma unroll
    for (int u = 0; u < U; u++) {
        cd[u] = dtp[u]; cx[u] = xp[u];
        cB[u] = bcp[(size_t)u*XW]; cC[u] = bcp[(size_t)u*XW + NST];
    }
    for (int l0 = 0; l0 < L_; l0 += U) {
        float nd[U], nx[U], nB[U], nC[U];
        int l1 = l0 + U;
        if (l1 < L_) {
            #pragma unroll
            for (int u = 0; u < U; u++) {
                nd[u] = dtp[l1+u]; nx[u] = xp[l1+u];
                nB[u] = bcp[(size_t)(l1+u)*XW]; nC[u] = bcp[(size_t)(l1+u)*XW + NST];
            }
        }
        #pragma unroll
        for (int u = 0; u < U; u++) {
            float dt = cd[u], xv = cx[u];
            float dA = __expf(dt * a);
            float p  = dt * xv * cB[u];
            h = fmaf(h, dA, p);
            float y = h * cC[u];
            y += __shfl_xor_sync(0xffffffffu, y, 8);
            y += __shfl_xor_sync(0xffffffffu, y, 4);
            y += __shfl_xor_sync(0xffffffffu, y, 2);
            y += __shfl_xor_sync(0xffffffffu, y, 1);
            if (n == 0) yp[l0 + u] = fmaf(xv, Dd, y);
        }
        if (l1 < L_) {
            #pragma unroll
            for (int u = 0; u < U; u++) { cd[u]=nd[u]; cx[u]=nx[u]; cB[u]=nB[u]; cC[u]=nC[u]; }
        }
    }
}

// ---------------- 8) GEMM: out = (y .* silu(z)) @ W_out^T, store transposed (b,c,l) ----------------
__global__ void gemm_out_kernel(const float* __restrict__ Wout, float* __restrict__ out) {
    __shared__ __align__(16) float As[8][128];
    __shared__ float Zs[8][129];
    __shared__ __align__(16) float Bs[8][128];
    int bm = blockIdx.y, bn = blockIdx.x;
    int row0 = bm * 128;
    int b = row0 / L_, l0 = row0 % L_;
    int tid = threadIdx.x;
    int tc = tid & 15, tr = tid >> 4;
    u64 acc[8][4];
    #pragma unroll
    for (int i = 0; i < 8; i++)
        #pragma unroll
        for (int j = 0; j < 4; j++) acc[i][j] = 0ull;
    int lr = tid >> 1;
    int lk = (tid & 1) * 4;
    const float* Wg = Wout + ((size_t)bn*128 + lr)*DIN + lk;
    for (int k0 = 0; k0 < DIN; k0 += 8) {
        {   // y tile: coalesced along l from (b,d,l)
            int l_off = tid & 127, kb = tid >> 7;   // kb 0..1
            #pragma unroll
            for (int q = 0; q < 4; q++) {
                int kq = kb + q*2;
                As[kq][l_off] = g_yt[((size_t)(b*DIN + k0 + kq))*L_ + l0 + l_off];
            }
        }
        {   // z tile: coalesced along d from (b*l, d); fold silu
            #pragma unroll
            for (int q = 0; q < 4; q++) {
                int idx = tid + q*256;
                int kk = idx & 7, lo = idx >> 3;
                float zv = g_z[(size_t)(row0 + lo)*DIN + k0 + kk];
                Zs[kk][lo] = silu_f(zv);
            }
        }
        float4 bv = *(const float4*)(Wg + k0);
        Bs[lk+0][lr]=bv.x; Bs[lk+1][lr]=bv.y; Bs[lk+2][lr]=bv.z; Bs[lk+3][lr]=bv.w;
        __syncthreads();
        #pragma unroll
        for (int q = 0; q < 4; q++) {   // A *= silu(z)
            int idx = tid + q*256;
            int lo = idx & 127, kk = idx >> 7;
            As[kk][lo] *= Zs[kk][lo];
        }
        __syncthreads();
        #pragma unroll
        for (int k = 0; k < 8; k++) {
            float ar[8];
            *(float4*)&ar[0] = *(const float4*)&As[k][tr*8];
            *(float4*)&ar[4] = *(const float4*)&As[k][tr*8+4];
            u64 br[4];
            *(float4*)&br[0] = *(const float4*)&Bs[k][tc*8];
            *(float4*)&br[2] = *(const float4*)&Bs[k][tc*8+4];
            #pragma unroll
            for (int i = 0; i < 8; i++) {
                u64 ai = pack2(ar[i], ar[i]);
                #pragma unroll
                for (int j = 0; j < 4; j++) ffma2(acc[i][j], ai, br[j]);
            }
        }
        __syncthreads();
    }
    // epilogue: out[b][c][l] with l-contiguous vector stores
    int lbase = l0 + tr*8;
    #pragma unroll
    for (int j = 0; j < 4; j++) {
        float2 p[8];
        #pragma unroll
        for (int i = 0; i < 8; i++) p[i] = unpack2(acc[i][j]);
        int c0g = bn*128 + tc*8 + 2*j;
        float* o0 = out + ((size_t)(b*C_ + c0g))  *L_ + lbase;
        float* o1 = out + ((size_t)(b*C_ + c0g+1))*L_ + lbase;
        float4 lo0 = {p[0].x, p[1].x, p[2].x, p[3].x};
        float4 lo1 = {p[4].x, p[5].x, p[6].x, p[7].x};
        float4 hi0 = {p[0].y, p[1].y, p[2].y, p[3].y};
        float4 hi1 = {p[4].y, p[5].y, p[6].y, p[7].y};
        *(float4*)o0 = lo0; *(float4*)(o0+4) = lo1;
        *(float4*)o1 = hi0; *(float4*)(o1+4) = hi1;
    }
}

// ---------------- launch ----------------
extern "C" void kernel_launch(void* const* d_in, const int* in_sizes, int n_in,
                              void* d_out, int out_size) {
    const float* x      = (const float*)d_in[0];
    const float* ln_w   = (const float*)d_in[1];
    const float* ln_b   = (const float*)d_in[2];
    const float* W_in   = (const float*)d_in[3];
    const float* conv_w = (const float*)d_in[4];
    const float* conv_b = (const float*)d_in[5];
    const float* W_xprj = (const float*)d_in[6];
    const float* W_dt   = (const float*)d_in[7];
    const float* b_dt   = (const float*)d_in[8];
    const float* A_log  = (const float*)d_in[9];
    const float* Dp     = (const float*)d_in[10];
    const float* W_out  = (const float*)d_in[11];
    float* out = (float*)d_out;

    ln_stats_kernel<<<(B_*L_)/256, 256>>>(x);
    ln_apply_kernel<<<dim3(C_/32, L_/32, B_), 256>>>(x, ln_w, ln_b);
    gemm_in_kernel<<<dim3((2*DIN)/128, (B_*L_)/128), 256>>>(W_in);
    conv_silu_kernel<<<dim3(L_/64, DIN/32, B_), 256>>>(conv_w, conv_b);
    gemm_xproj_kernel<<<(B_*L_)/128, 256>>>(W_xprj);
    dt_kernel<<<dim3(L_/32, DIN/64, B_), 256>>>(W_dt, b_dt);
    scan_kernel<<<(B_*DIN/2)*32/128, 128>>>(A_log, Dp);
    gemm_out_kernel<<<dim3(C_/128, (B_*L_)/128), 256>>>(W_out, out);
}

// round 3
// speedup vs baseline: 1.7741x; 1.7741x over previous
#include <cuda_runtime.h>
#include <cuda_bf16.h>
#include <cstdint>

#define B_   2
#define C_   384
#define L_   8192
#define DIN  768
#define NST  16
#define DTR  24
#define XW   56        // dt_rank + 2*d_state

// ---------------- scratch (device globals; no allocation allowed) ----------------
__device__ float g_stats[B_*L_*2];
__device__ float g_xi  [(size_t)B_*L_*DIN];    // (b*l, d)
__device__ float g_z   [(size_t)B_*L_*DIN];    // (b*l, d)
__device__ float g_xct [(size_t)B_*DIN*L_];    // (b, d, l)  conv+silu output
__device__ float g_xdbl[(size_t)B_*L_*XW];     // (b*l, 56)
__device__ float g_dtt [(size_t)B_*DIN*L_];    // (b, d, l)  softplus(dt)
__device__ float g_yt  [(size_t)B_*DIN*L_];    // (b, d, l)  scan out + x*D (pre-gate)

// bf16 split operands for tensor-core GEMMs
__device__ __nv_bfloat16 g_xnh[(size_t)B_*L_*C_], g_xnl[(size_t)B_*L_*C_];       // xn   (b*l, c)
__device__ __nv_bfloat16 g_winh[(size_t)2*DIN*C_], g_winl[(size_t)2*DIN*C_];     // W_in (2*din, c)
__device__ __nv_bfloat16 g_gh [(size_t)B_*L_*DIN], g_gl [(size_t)B_*L_*DIN];     // y*silu(z) (b*l, d)
__device__ __nv_bfloat16 g_wouth[(size_t)C_*DIN], g_woutl[(size_t)C_*DIN];       // W_out (c, din)

__device__ __forceinline__ float silu_f(float v) {
    return v * (1.f / (1.f + __expf(-v)));
}
__device__ __forceinline__ uint32_t smem_u32(const void* p) {
    uint32_t a;
    asm("{ .reg .u64 t; cvta.to.shared.u64 t, %1; cvt.u32.u64 %0, t; }" : "=r"(a) : "l"(p));
    return a;
}

// ================= HMMA building blocks (sm_80-era PTX, legal on base sm_103) =================
#define CP16(dst, src) \
    asm volatile("cp.async.cg.shared.global [%0], [%1], 16;" :: "r"(dst), "l"(src))
#define CP_COMMIT() asm volatile("cp.async.commit_group;" ::: "memory")
#define CP_WAIT1()  asm volatile("cp.async.wait_group 1;" ::: "memory")
#define CP_WAIT0()  asm volatile("cp.async.wait_group 0;" ::: "memory")

__device__ __forceinline__ void ldsm4(uint32_t r[4], uint32_t addr) {
    asm volatile("ldmatrix.sync.aligned.m8n8.x4.shared.b16 {%0,%1,%2,%3}, [%4];"
        : "=r"(r[0]), "=r"(r[1]), "=r"(r[2]), "=r"(r[3]) : "r"(addr));
}
__device__ __forceinline__ void mma16816(float d[4], const uint32_t a[4],
                                         uint32_t b0, uint32_t b1) {
    asm volatile("mma.sync.aligned.m16n8k16.row.col.f32.bf16.bf16.f32 "
        "{%0,%1,%2,%3}, {%4,%5,%6,%7}, {%8,%9}, {%0,%1,%2,%3};"
        : "+f"(d[0]), "+f"(d[1]), "+f"(d[2]), "+f"(d[3])
        : "r"(a[0]), "r"(a[1]), "r"(a[2]), "r"(a[3]), "r"(b0), "r"(b1));
}

// Tile layout in each 32KB buffer: Ah @0, Al @8K, Bh @16K, Bl @24K.
// Each tile: 128 rows x 64B (32 bf16). 16B chunk ch swizzled: ch ^= (row>>1)&3.
__device__ __forceinline__ void stage_chunk(uint32_t sbuf,
        const __nv_bfloat16* __restrict__ Ah, const __nv_bfloat16* __restrict__ Al,
        int arow0, int lda,
        const __nv_bfloat16* __restrict__ Bh, const __nv_bfloat16* __restrict__ Bl,
        int brow0, int ldb, int kc, int tid) {
    const __nv_bfloat16* srcs[4] = {Ah, Al, Bh, Bl};
    #pragma unroll
    for (int tile = 0; tile < 4; tile++) {
        const __nv_bfloat16* src = srcs[tile];
        int ld = (tile < 2) ? lda : ldb;
        int r0 = (tile < 2) ? arow0 : brow0;
        #pragma unroll
        for (int h = 0; h < 2; h++) {
            int cid = tid + h * 256;        // 0..511
            int row = cid >> 2, ch = cid & 3;
            const void* g = src + (size_t)(r0 + row) * ld + kc * 32 + ch * 8;
            uint32_t d = sbuf + tile * 8192 + row * 64 + ((ch ^ ((row >> 1) & 3)) << 4);
            CP16(d, g);
        }
    }
}

// Compute one 32-k chunk: acc += Ah*Bh^T + Ah*Bl^T + Al*Bh^T  (warp tile 64x32)
__device__ __forceinline__ void compute_chunk(uint32_t sbuf, int warp_m, int warp_n,
                                              int lane, float acc[4][4][4]) {
    int arow = lane & 15;
    int akc  = lane >> 4;                       // 0/1
    int bro  = (lane & 7) + ((lane >> 4) << 3); // rows 0-7 then +8 for lanes>=16
    int bkc  = (lane >> 3) & 1;
    #pragma unroll
    for (int k16 = 0; k16 < 2; k16++) {
        uint32_t ah[4][4], al[4][4], bhf[2][4], blf[2][4];
        #pragma unroll
        for (int mi = 0; mi < 4; mi++) {
            int row = warp_m * 64 + mi * 16 + arow;
            int ch = k16 * 2 + akc;
            uint32_t off = row * 64 + ((ch ^ ((row >> 1) & 3)) << 4);
            ldsm4(ah[mi], sbuf + off);
            ldsm4(al[mi], sbuf + 8192 + off);
        }
        #pragma unroll
        for (int p = 0; p < 2; p++) {
            int row = warp_n * 32 + p * 16 + bro;
            int ch = k16 * 2 + bkc;
            uint32_t off = row * 64 + ((ch ^ ((row >> 1) & 3)) << 4);
            ldsm4(bhf[p], sbuf + 16384 + off);
            ldsm4(blf[p], sbuf + 24576 + off);
        }
        #pragma unroll
        for (int mi = 0; mi < 4; mi++)
            #pragma unroll
            for (int nj = 0; nj < 4; nj++) {
                int p = nj >> 1, w = (nj & 1) * 2;
                mma16816(acc[mi][nj], ah[mi], bhf[p][w], bhf[p][w + 1]);
                mma16816(acc[mi][nj], ah[mi], blf[p][w], blf[p][w + 1]);
                mma16816(acc[mi][nj], al[mi], bhf[p][w], bhf[p][w + 1]);
            }
    }
}

// Full mainloop: D[128x128] = A[128,K] (row-major, ld=lda) x B[128,K]^T (ld=ldb)
__device__ __forceinline__ void mma_mainloop(char* smem, int tid,
        const __nv_bfloat16* Ah, const __nv_bfloat16* Al, int arow0, int lda,
        const __nv_bfloat16* Bh, const __nv_bfloat16* Bl, int brow0, int ldb,
        int nch, float acc[4][4][4]) {
    uint32_t sb = smem_u32(smem);
    int warp_m = (tid >> 5) >> 2, warp_n = (tid >> 5) & 3, lane = tid & 31;
    #pragma unroll
    for (int mi = 0; mi < 4; mi++)
        #pragma unroll
        for (int nj = 0; nj < 4; nj++)
            #pragma unroll
            for (int r = 0; r < 4; r++) acc[mi][nj][r] = 0.f;
    stage_chunk(sb, Ah, Al, arow0, lda, Bh, Bl, brow0, ldb, 0, tid);
    CP_COMMIT();
    for (int c = 0; c < nch; c++) {
        if (c + 1 < nch) {
            stage_chunk(sb + ((c + 1) & 1) * 32768, Ah, Al, arow0, lda,
                        Bh, Bl, brow0, ldb, c + 1, tid);
            CP_COMMIT();
            CP_WAIT1();
        } else {
            CP_WAIT0();
        }
        __syncthreads();
        compute_chunk(sb + (c & 1) * 32768, warp_m, warp_n, lane, acc);
        __syncthreads();
    }
}

#define SMEM_HMMA (2 * 32768)

// ---------------- tensor GEMM 1: xz = xn @ W_in^T -> g_xi / g_z ----------------
__global__ void __launch_bounds__(256) hmma_gemm_in_kernel() {
    extern __shared__ char smem[];
    int tid = threadIdx.x;
    int bn = blockIdx.x, bm = blockIdx.y;
    float acc[4][4][4];
    mma_mainloop(smem, tid, g_xnh, g_xnl, bm * 128, C_,
                 g_winh, g_winl, bn * 128, C_, C_ / 32, acc);
    int warp_m = (tid >> 5) >> 2, warp_n = (tid >> 5) & 3, lane = tid & 31;
    int g = lane >> 2, t = lane & 3;
    int col0 = bn * 128;
    float* dst = (col0 < DIN) ? g_xi : g_z;
    int cbase = ((col0 < DIN) ? col0 : col0 - DIN) + warp_n * 32;
    #pragma unroll
    for (int mi = 0; mi < 4; mi++) {
        int row = bm * 128 + warp_m * 64 + mi * 16 + g;
        #pragma unroll
        for (int nj = 0; nj < 4; nj++) {
            int col = cbase + nj * 8 + 2 * t;
            *(float2*)(dst + (size_t)row * DIN + col)       = make_float2(acc[mi][nj][0], acc[mi][nj][1]);
            *(float2*)(dst + (size_t)(row + 8) * DIN + col) = make_float2(acc[mi][nj][2], acc[mi][nj][3]);
        }
    }
}

// ---------------- tensor GEMM 2: out = W_out x gate^T, store (b,c,l) ----------------
// A = W_out (M=c), B = gate rows (N = b*l) -> l-contiguous stores.
__global__ void __launch_bounds__(256) hmma_gemm_out_kernel(float* __restrict__ out) {
    extern __shared__ char smem[];
    int tid = threadIdx.x;
    int bn = blockIdx.x, bm = blockIdx.y;
    float acc[4][4][4];
    mma_mainloop(smem, tid, g_wouth, g_woutl, bm * 128, DIN,
                 g_gh, g_gl, bn * 128, DIN, DIN / 32, acc);
    int warp_m = (tid >> 5) >> 2, warp_n = (tid >> 5) & 3, lane = tid & 31;
    int g = lane >> 2, t = lane & 3;
    int nrow0 = bn * 128 + warp_n * 32;
    int b = nrow0 / L_;
    #pragma unroll
    for (int mi = 0; mi < 4; mi++) {
        int c = bm * 128 + warp_m * 64 + mi * 16 + g;
        #pragma unroll
        for (int nj = 0; nj < 4; nj++) {
            int l = (nrow0 % L_) + nj * 8 + 2 * t;
            *(float2*)(out + ((size_t)(b * C_ + c)) * L_ + l)     = make_float2(acc[mi][nj][0], acc[mi][nj][1]);
            *(float2*)(out + ((size_t)(b * C_ + c + 8)) * L_ + l) = make_float2(acc[mi][nj][2], acc[mi][nj][3]);
        }
    }
}

// ---------------- weight split fp32 -> (hi, lo) bf16 ----------------
__global__ void cvt_split_kernel(const float* __restrict__ w, __nv_bfloat16* __restrict__ h,
                                 __nv_bfloat16* __restrict__ l, int n) {
    int i = blockIdx.x * 256 + threadIdx.x;
    if (i < n) {
        float v = w[i];
        __nv_bfloat16 hi = __float2bfloat16(v);
        h[i] = hi;
        l[i] = __float2bfloat16(v - __bfloat162float(hi));
    }
}

// ---------------- 1) LayerNorm stats ----------------
__global__ void ln_stats_kernel(const float* __restrict__ x) {
    int t = blockIdx.x * blockDim.x + threadIdx.x;
    int b = t / L_, l = t % L_;
    const float* p = x + (size_t)b * C_ * L_ + l;
    float s = 0.f, ss = 0.f;
    #pragma unroll 4
    for (int c = 0; c < C_; c++) { float v = p[(size_t)c * L_]; s += v; ss += v * v; }
    float mu = s * (1.f / C_);
    float var = ss * (1.f / C_) - mu * mu;
    g_stats[2*t]   = mu;
    g_stats[2*t+1] = rsqrtf(var + 1e-5f);
}

// ---------------- 2) LayerNorm apply + transpose + bf16 split ----------------
__global__ void ln_apply_kernel(const float* __restrict__ x, const float* __restrict__ w,
                                const float* __restrict__ bb) {
    __shared__ float t[32][33];
    int c0 = blockIdx.x * 32, l0 = blockIdx.y * 32, b = blockIdx.z;
    int tx = threadIdx.x & 31, ty = threadIdx.x >> 5;
    const float* xb = x + (size_t)b * C_ * L_;
    #pragma unroll
    for (int p = 0; p < 4; p++) {
        int c = c0 + ty + p*8;
        t[ty + p*8][tx] = xb[(size_t)c * L_ + l0 + tx];
    }
    __syncthreads();
    #pragma unroll
    for (int p = 0; p < 4; p++) {
        int l = l0 + ty + p*8;
        int c = c0 + tx;
        int li = b * L_ + l;
        float mu = g_stats[2*li], rs = g_stats[2*li+1];
        float v = (t[tx][ty + p*8] - mu) * rs * w[c] + bb[c];
        __nv_bfloat16 hi = __float2bfloat16(v);
        g_xnh[(size_t)li * C_ + c] = hi;
        g_xnl[(size_t)li * C_ + c] = __float2bfloat16(v - __bfloat162float(hi));
    }
}

// ---------------- 4) depthwise causal conv (k=4) + SiLU, (b,l,d) -> (b,d,l) ----------------
__global__ void conv_silu_kernel(const float* __restrict__ cw, const float* __restrict__ cb) {
    __shared__ float s[67][33];
    int l0 = blockIdx.x * 64, d0 = blockIdx.y * 32, b = blockIdx.z;
    int tid = threadIdx.x;
    for (int idx = tid; idx < 67*32; idx += 256) {
        int li = idx >> 5, dd = idx & 31;
        int gl = l0 + li - 3;
        s[li][dd] = (gl >= 0) ? g_xi[((size_t)(b*L_ + gl))*DIN + d0 + dd] : 0.f;
    }
    __syncthreads();
    for (int idx = tid; idx < 2048; idx += 256) {
        int dd = idx >> 6, ll = idx & 63;
        int d = d0 + dd;
        float w0 = cw[d*4], w1 = cw[d*4+1], w2 = cw[d*4+2], w3 = cw[d*4+3];
        float acc = cb[d];
        acc += w0*s[ll][dd] + w1*s[ll+1][dd] + w2*s[ll+2][dd] + w3*s[ll+3][dd];
        g_xct[((size_t)(b*DIN + d))*L_ + l0 + ll] = silu_f(acc);
    }
}

// ---------------- 5) GEMM: x_dbl = xc @ W_xproj^T ----------------
__global__ void gemm_xproj_kernel(const float* __restrict__ Wx) {
    __shared__ float As[16][128];
    __shared__ float Bs[16][56];
    int row0 = blockIdx.x * 128;
    int b = row0 / L_, l0 = row0 % L_;
    int tid = threadIdx.x;
    float acc[4][7];
    #pragma unroll
    for (int i = 0; i < 4; i++)
        #pragma unroll
        for (int j = 0; j < 7; j++) acc[i][j] = 0.f;
    int mr = (tid >> 3) * 4;
    int nc = (tid & 7) * 7;
    for (int k0 = 0; k0 < DIN; k0 += 16) {
        for (int idx = tid; idx < 2048; idx += 256) {
            int kk = idx >> 7, lo = idx & 127;
            As[kk][lo] = g_xct[((size_t)(b*DIN + k0 + kk))*L_ + l0 + lo];
        }
        for (int idx = tid; idx < 896; idx += 256) {
            int r = idx / 16, kk = idx % 16;
            Bs[kk][r] = Wx[(size_t)r*DIN + k0 + kk];
        }
        __syncthreads();
        #pragma unroll
        for (int k = 0; k < 16; k++) {
            float ar[4], br[7];
            #pragma unroll
            for (int i = 0; i < 4; i++) ar[i] = As[k][mr+i];
            #pragma unroll
            for (int j = 0; j < 7; j++) br[j] = Bs[k][nc+j];
            #pragma unroll
            for (int i = 0; i < 4; i++)
                #pragma unroll
                for (int j = 0; j < 7; j++) acc[i][j] = fmaf(ar[i], br[j], acc[i][j]);
        }
        __syncthreads();
    }
    #pragma unroll
    for (int i = 0; i < 4; i++)
        #pragma unroll
        for (int j = 0; j < 7; j++)
            g_xdbl[(size_t)(row0 + mr + i)*XW + nc + j] = acc[i][j];
}

// ---------------- 6) dt = softplus(...) -> (b,d,l) ----------------
__global__ void dt_kernel(const float* __restrict__ Wdt, const float* __restrict__ bdt) {
    __shared__ float xs[32][25];
    __shared__ float ws[64][24];
    __shared__ float bs[64];
    int l0 = blockIdx.x * 32, d0 = blockIdx.y * 64, b = blockIdx.z;
    int tid = threadIdx.x;
    for (int idx = tid; idx < 32*24; idx += 256) {
        int ll = idx / 24, r = idx % 24;
        xs[ll][r] = g_xdbl[(size_t)(b*L_ + l0 + ll)*XW + r];
    }
    for (int idx = tid; idx < 64*24; idx += 256) {
        int dd = idx / 24, r = idx % 24;
        ws[dd][r] = Wdt[(size_t)(d0+dd)*DTR + r];
    }
    if (tid < 64) bs[tid] = bdt[d0 + tid];
    __syncthreads();
    #pragma unroll
    for (int t = 0; t < 8; t++) {
        int idx = tid + t*256;
        int dd = idx >> 5, ll = idx & 31;
        float acc = bs[dd];
        #pragma unroll
        for (int r = 0; r < 24; r++) acc = fmaf(xs[ll][r], ws[dd][r], acc);
        float sp = (acc > 20.f) ? acc : log1pf(expf(acc));
        g_dtt[((size_t)(b*DIN + d0 + dd))*L_ + l0 + ll] = sp;
    }
}

// ---------------- 7) selective scan ----------------
__global__ void scan_kernel(const float* __restrict__ Alog, const float* __restrict__ Dp) {
    int gw = (blockIdx.x * blockDim.x + threadIdx.x) >> 5;
    int lane = threadIdx.x & 31;
    int half = lane >> 4, n = lane & 15;
    int b = gw / (DIN/2);
    int d = (gw % (DIN/2)) * 2 + half;
    const float* dtp = g_dtt + (size_t)(b*DIN + d) * L_;
    const float* xp  = g_xct + (size_t)(b*DIN + d) * L_;
    const float* bcp = g_xdbl + (size_t)b * L_ * XW + DTR + n;
    float a  = -__expf(Alog[d*NST + n]);
    float Dd = Dp[d];
    float* yp = g_yt + (size_t)(b*DIN + d) * L_;
    float h = 0.f;
    const int U = 8;
    float cd[U], cx[U], cB[U], cC[U];
    #pragma unroll
    for (int u = 0; u < U; u++) {
        cd[u] = dtp[u]; cx[u] = xp[u];
        cB[u] = bcp[(size_t)u*XW]; cC[u] = bcp[(size_t)u*XW + NST];
    }
    for (int l0 = 0; l0 < L_; l0 += U) {
        float nd[U], nx[U], nB[U], nC[U];
        int l1 = l0 + U;
        if (l1 < L_) {
            #pragma unroll
            for (int u = 0; u < U; u++) {
                nd[u] = dtp[l1+u]; nx[u] = xp[l1+u];
                nB[u] = bcp[(size_t)(l1+u)*XW]; nC[u] = bcp[(size_t)(l1+u)*XW + NST];
            }
        }
        #pragma unroll
        for (int u = 0; u < U; u++) {
            float dt = cd[u], xv = cx[u];
            float dA = __expf(dt * a);
            float p  = dt * xv * cB[u];
            h = fmaf(h, dA, p);
            float y = h * cC[u];
            y += __shfl_xor_sync(0xffffffffu, y, 8);
            y += __shfl_xor_sync(0xffffffffu, y, 4);
            y += __shfl_xor_sync(0xffffffffu, y, 2);
            y += __shfl_xor_sync(0xffffffffu, y, 1);
            if (n == 0) yp[l0 + u] = fmaf(xv, Dd, y);
        }
        if (l1 < L_) {
            #pragma unroll
            for (int u = 0; u < U; u++) { cd[u]=nd[u]; cx[u]=nx[u]; cB[u]=nB[u]; cC[u]=nC[u]; }
        }
    }
}

// ---------------- 8) gate: g = y * silu(z), transpose (b,d,l)->(b*l,d), bf16 split ----------------
__global__ void gate_cvt_kernel() {
    __shared__ float sy[32][33];
    int l0 = blockIdx.x * 32, d0 = blockIdx.y * 32, b = blockIdx.z;
    int tx = threadIdx.x & 31, ty = threadIdx.x >> 5;
    #pragma unroll
    for (int p = 0; p < 4; p++) {
        int d = d0 + ty + p*8;
        sy[ty + p*8][tx] = g_yt[((size_t)(b*DIN + d))*L_ + l0 + tx];
    }
    __syncthreads();
    #pragma unroll
    for (int p = 0; p < 4; p++) {
        int l = l0 + ty + p*8;
        int d = d0 + tx;
        size_t idx = (size_t)(b*L_ + l)*DIN + d;
        float zv = g_z[idx];
        float g = sy[tx][ty + p*8] * silu_f(zv);
        __nv_bfloat16 hi = __float2bfloat16(g);
        g_gh[idx] = hi;
        g_gl[idx] = __float2bfloat16(g - __bfloat162float(hi));
    }
}

// ---------------- launch ----------------
extern "C" void kernel_launch(void* const* d_in, const int* in_sizes, int n_in,
                              void* d_out, int out_size) {
    const float* x      = (const float*)d_in[0];
    const float* ln_w   = (const float*)d_in[1];
    const float* ln_b   = (const float*)d_in[2];
    const float* W_in   = (const float*)d_in[3];
    const float* conv_w = (const float*)d_in[4];
    const float* conv_b = (const float*)d_in[5];
    const float* W_xprj = (const float*)d_in[6];
    const float* W_dt   = (const float*)d_in[7];
    const float* b_dt   = (const float*)d_in[8];
    const float* A_log  = (const float*)d_in[9];
    const float* Dp     = (const float*)d_in[10];
    const float* W_out  = (const float*)d_in[11];
    float* out = (float*)d_out;

    static int smem_set = 0;
    if (!smem_set) {
        cudaFuncSetAttribute(hmma_gemm_in_kernel,  cudaFuncAttributeMaxDynamicSharedMemorySize, SMEM_HMMA);
        cudaFuncSetAttribute(hmma_gemm_out_kernel, cudaFuncAttributeMaxDynamicSharedMemorySize, SMEM_HMMA);
        smem_set = 1;
    }

    __nv_bfloat16 *winh, *winl, *wouth, *woutl;
    cudaGetSymbolAddress((void**)&winh,  g_winh);
    cudaGetSymbolAddress((void**)&winl,  g_winl);
    cudaGetSymbolAddress((void**)&wouth, g_wouth);
    cudaGetSymbolAddress((void**)&woutl, g_woutl);

    cvt_split_kernel<<<(2*DIN*C_ + 255)/256, 256>>>(W_in,  winh,  winl,  2*DIN*C_);
    cvt_split_kernel<<<(C_*DIN   + 255)/256, 256>>>(W_out, wouth, woutl, C_*DIN);
    ln_stats_kernel<<<(B_*L_)/256, 256>>>(x);
    ln_apply_kernel<<<dim3(C_/32, L_/32, B_), 256>>>(x, ln_w, ln_b);
    hmma_gemm_in_kernel<<<dim3((2*DIN)/128, (B_*L_)/128), 256, SMEM_HMMA>>>();
    conv_silu_kernel<<<dim3(L_/64, DIN/32, B_), 256>>>(conv_w, conv_b);
    gemm_xproj_kernel<<<(B_*L_)/128, 256>>>(W_xprj);
    dt_kernel<<<dim3(L_/32, DIN/64, B_), 256>>>(W_dt, b_dt);
    scan_kernel<<<(B_*DIN/2)*32/128, 128>>>(A_log, Dp);
    gate_cvt_kernel<<<dim3(L_/32, DIN/32, B_), 256>>>();
    hmma_gemm_out_kernel<<<dim3((B_*L_)/128, C_/128), 256, SMEM_HMMA>>>(out);
}